// round 9
// baseline (speedup 1.0000x reference)
#include <cuda_runtime.h>
#include <math.h>

#define Bdim 1024
#define Ndim 1024
#define Mdim 64
#define EPSV 1e-16f
#define COS_EPS 1e-8f
#define HALF_N 512

#define CLUSTER_SYNC() do { \
    asm volatile("barrier.cluster.arrive.aligned;" ::: "memory"); \
    asm volatile("barrier.cluster.wait.aligned;"   ::: "memory"); } while (0)

// Store one float into the PEER CTA's shared variable (same smem offset).
__device__ __forceinline__ void st_peer_f32(void* myaddr, unsigned peer, float v) {
    unsigned a = (unsigned)__cvta_generic_to_shared(myaddr);
    unsigned pa;
    asm("mapa.shared::cluster.u32 %0, %1, %2;" : "=r"(pa) : "r"(a), "r"(peer));
    asm volatile("st.shared::cluster.f32 [%0], %1;" :: "r"(pa), "f"(v));
}

// ---------------------------------------------------------------------------
// Block-wide SUM reduction for 512 threads, 2 barriers.
// ---------------------------------------------------------------------------
__device__ __forceinline__ float blk_sum512(float v, float* red, int tid) {
    const int lane = tid & 31, warp = tid >> 5;   // 16 warps
#pragma unroll
    for (int o = 16; o > 0; o >>= 1)
        v += __shfl_xor_sync(0xffffffffu, v, o);
    if (lane == 0) red[warp] = v;
    __syncthreads();
    if (warp == 0) {
        float t = (lane < 16) ? red[lane] : 0.f;
#pragma unroll
        for (int o = 8; o > 0; o >>= 1)
            t += __shfl_xor_sync(0xffffffffu, t, o);
        if (lane == 0) red[16] = t;
    }
    __syncthreads();
    return red[16];
}

// ---------------------------------------------------------------------------
// Fused NTM step: 2-CTA cluster per batch, each CTA owns 512 rows.
// 512 threads, 2 CTAs/SM.
// ---------------------------------------------------------------------------
__global__ void __launch_bounds__(512, 2) __cluster_dims__(2, 1, 1)
fused_ntm(const float* __restrict__ mem,   const float* __restrict__ kk,
          const float* __restrict__ beta,  const float* __restrict__ gg,
          const float* __restrict__ ss,    const float* __restrict__ gamma,
          const float* __restrict__ wprev, const float* __restrict__ ee,
          const float* __restrict__ aa,    float* __restrict__ out) {
    const int b        = blockIdx.x >> 1;       // batch
    const unsigned rank = blockIdx.x & 1;        // cluster rank
    const unsigned peer = rank ^ 1;
    const int tid = threadIdx.x;
    const int ml  = tid & 15;                    // float4 lane within a row
    const int rg  = tid >> 4;                    // row group 0..31
    const int row0 = rank * HALF_N;              // first global row of this CTA

    __shared__ float  s_sc[HALF_N];
    __shared__ float  s_wg[HALF_N];
    __shared__ float  s_w [HALF_N];
    __shared__ float  redA[17];
    __shared__ float  redB[17];
    __shared__ float4 s_r[512];
    __shared__ float  m_E, m_W, m_lo, m_hi;      // peer mailboxes
    __shared__ float4 m_read[16];

    const float* mb = mem + (size_t)b * Ndim * Mdim;

    // ---- early loads: per-b scalars, wprev (register), e/a vectors ----
    const float wp  = __ldg(wprev + b * Ndim + row0 + tid);
    const float bet = beta[b];
    const float gv  = gg[b];
    const float gm  = gamma[b];
    const float sh0 = ss[b * 3 + 0], sh1 = ss[b * 3 + 1], sh2 = ss[b * 3 + 2];
    const float4 e4 = *(const float4*)(ee + b * Mdim + ml * 4);
    const float4 a4 = *(const float4*)(aa + b * Mdim + ml * 4);

    // ---- k (+eps) and its norm (reduced within each 16-lane group) ----
    float4 k4 = *(const float4*)(kk + b * Mdim + ml * 4);
    const float kx = k4.x + EPSV, ky = k4.y + EPSV;
    const float kz = k4.z + EPSV, kw = k4.w + EPSV;
    float kn = kx * kx + ky * ky + kz * kz + kw * kw;
#pragma unroll
    for (int o = 8; o > 0; o >>= 1) kn += __shfl_xor_sync(0xffffffffu, kn, o);
    const float knorm = fmaxf(sqrtf(kn), COS_EPS);

    // ---- Phase 1: scores for own 512 rows. 2 groups x 8 batched LDG.128,
    //      butterfly reduce-scatter over the 16-lane group ----
#pragma unroll
    for (int grp = 0; grp < 2; grp++) {
        float4 m[8];
#pragma unroll
        for (int j = 0; j < 8; j++) {
            const int n = row0 + grp * 256 + j * 32 + rg;
            m[j] = *(const float4*)(mb + (size_t)n * Mdim + ml * 4);
        }
        float v[16];
#pragma unroll
        for (int j = 0; j < 8; j++) {
            const float ax = m[j].x + EPSV, ay = m[j].y + EPSV;
            const float az = m[j].z + EPSV, aw = m[j].w + EPSV;
            float d = ax * kx; d = fmaf(ay, ky, d); d = fmaf(az, kz, d); d = fmaf(aw, kw, d);
            float s = ax * ax; s = fmaf(ay, ay, s); s = fmaf(az, az, s); s = fmaf(aw, aw, s);
            v[j]     = d;
            v[8 + j] = s;
        }
        int cnt = 16;
#pragma unroll
        for (int o = 8; o >= 1; o >>= 1) {
            cnt >>= 1;
            const bool hi = (ml & o);
#pragma unroll
            for (int i = 0; i < cnt; i++) {
                const float send = hi ? v[i] : v[i + cnt];
                const float recv = __shfl_xor_sync(0xffffffffu, send, o);
                v[i] = (hi ? v[i + cnt] : v[i]) + recv;
            }
        }
        const float other = __shfl_xor_sync(0xffffffffu, v[0], 8);
        if (ml < 8)
            s_sc[grp * 256 + ml * 32 + rg] =
                bet * (v[0] / (fmaxf(sqrtf(other), COS_EPS) * knorm));
    }
    __syncthreads();

    // ---- Phase 2: softmax (no max: |score| <= ~1) across the cluster ----
    const float ex = __expf(s_sc[tid]);
    const float E  = blk_sum512(ex, redA, tid);
    if (tid == 0) st_peer_f32(&m_E, peer, E);
    CLUSTER_SYNC();                                  // #1

    const float inv_esum = 1.f / (E + m_E);
    const float wg = fmaf(gv, ex * inv_esum - wp, wp);
    s_wg[tid] = wg;
    // peer's lo-neighbor is my last wg; peer's hi-neighbor is my first wg
    if (tid == HALF_N - 1) st_peer_f32(&m_lo, peer, wg);
    if (tid == 0)          st_peer_f32(&m_hi, peer, wg);
    CLUSTER_SYNC();                                  // #2

    const float lo = (tid == 0)          ? m_lo : s_wg[tid - 1];
    const float hi = (tid == HALF_N - 1) ? m_hi : s_wg[tid + 1];
    const float w  = __powf(sh0 * lo + sh1 * wg + sh2 * hi, gm);
    const float W  = blk_sum512(w, redB, tid);
    if (tid == 0) st_peer_f32(&m_W, peer, W);
    CLUSTER_SYNC();                                  // #3

    s_w[tid] = w / (W + m_W + EPSV);
    __syncthreads();

    // ---- Phase 3: read vector + erase/add write (reverse order) ----
    float* ob = out + (size_t)b * (Ndim + 1) * Mdim;

    float rx = 0.f, ry = 0.f, rz = 0.f, rw = 0.f;
#pragma unroll
    for (int grp = 1; grp >= 0; grp--) {
        float4 m[8];
#pragma unroll
        for (int j = 0; j < 8; j++) {
            const int n = row0 + grp * 256 + j * 32 + rg;
            m[j] = __ldcs((const float4*)(mb + (size_t)n * Mdim + ml * 4));
        }
#pragma unroll
        for (int j = 0; j < 8; j++) {
            const int nl = grp * 256 + j * 32 + rg;
            const float wv = s_w[nl];
            float4 o4;
            o4.x = fmaf(m[j].x, fmaf(-wv, e4.x, 1.f), wv * a4.x);
            o4.y = fmaf(m[j].y, fmaf(-wv, e4.y, 1.f), wv * a4.y);
            o4.z = fmaf(m[j].z, fmaf(-wv, e4.z, 1.f), wv * a4.z);
            o4.w = fmaf(m[j].w, fmaf(-wv, e4.w, 1.f), wv * a4.w);
            __stcs((float4*)(ob + (size_t)(1 + row0 + nl) * Mdim + ml * 4), o4);
            rx = fmaf(wv, m[j].x, rx);
            ry = fmaf(wv, m[j].y, ry);
            rz = fmaf(wv, m[j].z, rz);
            rw = fmaf(wv, m[j].w, rw);
        }
    }

    // reduce read accumulators (512 -> 16 lanes of ml)
    s_r[tid] = make_float4(rx, ry, rz, rw);
    __syncthreads();
#pragma unroll
    for (int s = 256; s >= 16; s >>= 1) {
        if (tid < s) {
            float4 x = s_r[tid], y = s_r[tid + s];
            x.x += y.x; x.y += y.y; x.z += y.z; x.w += y.w;
            s_r[tid] = x;
        }
        __syncthreads();
    }
    // rank 1 ships its 64 partials to rank 0's mailbox
    if (rank == 1 && tid < 16) {
        float4 t = s_r[tid];
        st_peer_f32(&m_read[tid].x, peer, t.x);
        st_peer_f32(&m_read[tid].y, peer, t.y);
        st_peer_f32(&m_read[tid].z, peer, t.z);
        st_peer_f32(&m_read[tid].w, peer, t.w);
    }
    CLUSTER_SYNC();                                  // #4
    if (rank == 0 && tid < 16) {
        float4 t = s_r[tid], u = m_read[tid];
        t.x += u.x; t.y += u.y; t.z += u.z; t.w += u.w;
        __stcs((float4*)(ob + tid * 4), t);          // read row (row 0)
    }
}

// ---------------------------------------------------------------------------
extern "C" void kernel_launch(void* const* d_in, const int* in_sizes, int n_in,
                              void* d_out, int out_size) {
    const float* mem   = (const float*)d_in[0];
    const float* kk    = (const float*)d_in[1];
    const float* beta  = (const float*)d_in[2];
    const float* gg    = (const float*)d_in[3];
    const float* ss    = (const float*)d_in[4];
    const float* gamma = (const float*)d_in[5];
    const float* wprev = (const float*)d_in[6];
    const float* ee    = (const float*)d_in[7];
    const float* aa    = (const float*)d_in[8];
    float* out = (float*)d_out;

    fused_ntm<<<2 * Bdim, 512>>>(mem, kk, beta, gg, ss, gamma, wprev, ee, aa, out);
}

// round 10
// speedup vs baseline: 1.0492x; 1.0492x over previous
#include <cuda_runtime.h>
#include <math.h>

#define Bdim 1024
#define Ndim 1024
#define Mdim 64
#define EPSV 1e-16f
#define COS_EPS 1e-8f
#define HALF_N 512

#define CLUSTER_SYNC() do { \
    asm volatile("barrier.cluster.arrive.aligned;" ::: "memory"); \
    asm volatile("barrier.cluster.wait.aligned;"   ::: "memory"); } while (0)

// Store one float into the PEER CTA's shared variable (same smem offset).
__device__ __forceinline__ void st_peer_f32(void* myaddr, unsigned peer, float v) {
    unsigned a = (unsigned)__cvta_generic_to_shared(myaddr);
    unsigned pa;
    asm("mapa.shared::cluster.u32 %0, %1, %2;" : "=r"(pa) : "r"(a), "r"(peer));
    asm volatile("st.shared::cluster.f32 [%0], %1;" :: "r"(pa), "f"(v));
}

// ---------------------------------------------------------------------------
// Block-wide SUM reduction for 512 threads, 2 barriers.
// ---------------------------------------------------------------------------
__device__ __forceinline__ float blk_sum512(float v, float* red, int tid) {
    const int lane = tid & 31, warp = tid >> 5;   // 16 warps
#pragma unroll
    for (int o = 16; o > 0; o >>= 1)
        v += __shfl_xor_sync(0xffffffffu, v, o);
    if (lane == 0) red[warp] = v;
    __syncthreads();
    if (warp == 0) {
        float t = (lane < 16) ? red[lane] : 0.f;
#pragma unroll
        for (int o = 8; o > 0; o >>= 1)
            t += __shfl_xor_sync(0xffffffffu, t, o);
        if (lane == 0) red[16] = t;
    }
    __syncthreads();
    return red[16];
}

// ---------------------------------------------------------------------------
// Fused NTM step: 2-CTA cluster per batch.
// Phase 1 split by rows (512 each); phase 3 split by columns (32 each).
// ---------------------------------------------------------------------------
__global__ void __launch_bounds__(512, 2) __cluster_dims__(2, 1, 1)
fused_ntm(const float* __restrict__ mem,   const float* __restrict__ kk,
          const float* __restrict__ beta,  const float* __restrict__ gg,
          const float* __restrict__ ss,    const float* __restrict__ gamma,
          const float* __restrict__ wprev, const float* __restrict__ ee,
          const float* __restrict__ aa,    float* __restrict__ out) {
    const int b         = blockIdx.x >> 1;       // batch
    const unsigned rank = blockIdx.x & 1;        // cluster rank
    const unsigned peer = rank ^ 1;
    const int tid  = threadIdx.x;
    const int ml   = tid & 15;                   // P1: float4 lane (full row)
    const int rg   = tid >> 4;                   // P1: row group 0..31
    const int row0 = rank * HALF_N;              // first P1 row of this CTA

    __shared__ float  s_sc[HALF_N];              // own-half scores
    __shared__ float  s_wall[Ndim];              // full unnormalized w
    __shared__ float  redA[17];
    __shared__ float  redB[17];
    __shared__ float4 s_r[512];                  // P3 read-vector scratch
    __shared__ float  m_E, m_W, m_exf, m_exl;    // peer mailboxes

    const float* mb = mem + (size_t)b * Ndim * Mdim;

    // ---- early scalar loads ----
    const float wp  = __ldg(wprev + b * Ndim + row0 + tid);
    const float wp_lo = __ldg(wprev + b * Ndim + ((row0 + Ndim - 1) & (Ndim - 1)));
    const float wp_hi = __ldg(wprev + b * Ndim + ((row0 + HALF_N) & (Ndim - 1)));
    const float bet = beta[b];
    const float gv  = gg[b];
    const float gm  = gamma[b];
    const float sh0 = ss[b * 3 + 0], sh1 = ss[b * 3 + 1], sh2 = ss[b * 3 + 2];

    // ---- k (+eps) and its norm (reduced within each 16-lane group) ----
    float4 k4 = *(const float4*)(kk + b * Mdim + ml * 4);
    const float kx = k4.x + EPSV, ky = k4.y + EPSV;
    const float kz = k4.z + EPSV, kw = k4.w + EPSV;
    float kn = kx * kx + ky * ky + kz * kz + kw * kw;
#pragma unroll
    for (int o = 8; o > 0; o >>= 1) kn += __shfl_xor_sync(0xffffffffu, kn, o);
    const float knorm = fmaxf(sqrtf(kn), COS_EPS);

    // ---- Phase 1: scores for own 512 rows (butterfly reduce-scatter) ----
#pragma unroll
    for (int grp = 0; grp < 2; grp++) {
        float4 m[8];
#pragma unroll
        for (int j = 0; j < 8; j++) {
            const int n = row0 + grp * 256 + j * 32 + rg;
            m[j] = *(const float4*)(mb + (size_t)n * Mdim + ml * 4);
        }
        float v[16];
#pragma unroll
        for (int j = 0; j < 8; j++) {
            const float ax = m[j].x + EPSV, ay = m[j].y + EPSV;
            const float az = m[j].z + EPSV, aw = m[j].w + EPSV;
            float d = ax * kx; d = fmaf(ay, ky, d); d = fmaf(az, kz, d); d = fmaf(aw, kw, d);
            float s = ax * ax; s = fmaf(ay, ay, s); s = fmaf(az, az, s); s = fmaf(aw, aw, s);
            v[j]     = d;
            v[8 + j] = s;
        }
        int cnt = 16;
#pragma unroll
        for (int o = 8; o >= 1; o >>= 1) {
            cnt >>= 1;
            const bool hi = (ml & o);
#pragma unroll
            for (int i = 0; i < cnt; i++) {
                const float send = hi ? v[i] : v[i + cnt];
                const float recv = __shfl_xor_sync(0xffffffffu, send, o);
                v[i] = (hi ? v[i + cnt] : v[i]) + recv;
            }
        }
        const float other = __shfl_xor_sync(0xffffffffu, v[0], 8);
        if (ml < 8)
            s_sc[grp * 256 + ml * 32 + rg] =
                bet * (v[0] / (fmaxf(sqrtf(other), COS_EPS) * knorm));
    }
    __syncthreads();

    // ---- Phase 2a: local exp-sum; ship E + boundary ex to peer ----
    const float ex = __expf(s_sc[tid]);
    const float E  = blk_sum512(ex, redA, tid);
    if (tid == 0) {
        st_peer_f32(&m_E, peer, E);
        // peer's hi-neighbor ex is MY first ex
        st_peer_f32(&m_exf, peer, ex);
    }
    if (tid == HALF_N - 1) st_peer_f32(&m_exl, peer, ex);  // peer's lo-neighbor
    CLUSTER_SYNC();                                  // #1

    // ---- Phase 2b: interpolate + shift + sharpen; exchange w half + W ----
    const float inv_esum = 1.f / (E + m_E);
    const float wg = fmaf(gv, ex * inv_esum - wp, wp);
    s_sc[tid] = wg;                                  // reuse s_sc as wg buffer
    __syncthreads();

    // boundary wg values reconstructed from peer's boundary ex + gmem wprev
    const float wg_lo = (tid == 0)
        ? fmaf(gv, m_exl * inv_esum - wp_lo, wp_lo) : s_sc[(tid - 1) & (HALF_N - 1)];
    const float wg_hi = (tid == HALF_N - 1)
        ? fmaf(gv, m_exf * inv_esum - wp_hi, wp_hi) : s_sc[(tid + 1) & (HALF_N - 1)];
    const float w = __powf(sh0 * wg_lo + sh1 * wg + sh2 * wg_hi, gm);
    const float W = blk_sum512(w, redB, tid);

    s_wall[row0 + tid] = w;                          // own half locally
    st_peer_f32(&s_wall[row0 + tid], peer, w);       // fill peer's other half
    if (tid == 0) st_peer_f32(&m_W, peer, W);
    CLUSTER_SYNC();                                  // #2 (last cross-CTA access)

    const float inv_w = 1.f / (W + m_W + EPSV);

    // ---- Phase 3: all 1024 rows, own 32 columns (M-split) ----
    const int ml3 = tid & 7;                         // float4 lane in 32-col half
    const int rg3 = tid >> 3;                        // row group 0..63
    const int cb  = rank * 32 + ml3 * 4;             // column base

    const float4 e4 = *(const float4*)(ee + b * Mdim + cb);
    const float4 a4 = *(const float4*)(aa + b * Mdim + cb);
    float* ob = out + (size_t)b * (Ndim + 1) * Mdim;

    float rx = 0.f, ry = 0.f, rz = 0.f, rw = 0.f;
#pragma unroll
    for (int grp = 1; grp >= 0; grp--) {             // reverse for L2 reuse
        float4 m[8];
#pragma unroll
        for (int j = 0; j < 8; j++) {
            const int n = (grp * 8 + j) * 64 + rg3;
            m[j] = __ldcs((const float4*)(mb + (size_t)n * Mdim + cb));
        }
#pragma unroll
        for (int j = 0; j < 8; j++) {
            const int n = (grp * 8 + j) * 64 + rg3;
            const float wv = s_wall[n] * inv_w;
            float4 o4;
            o4.x = fmaf(m[j].x, fmaf(-wv, e4.x, 1.f), wv * a4.x);
            o4.y = fmaf(m[j].y, fmaf(-wv, e4.y, 1.f), wv * a4.y);
            o4.z = fmaf(m[j].z, fmaf(-wv, e4.z, 1.f), wv * a4.z);
            o4.w = fmaf(m[j].w, fmaf(-wv, e4.w, 1.f), wv * a4.w);
            __stcs((float4*)(ob + (size_t)(1 + n) * Mdim + cb), o4);
            rx = fmaf(wv, m[j].x, rx);
            ry = fmaf(wv, m[j].y, ry);
            rz = fmaf(wv, m[j].z, rz);
            rw = fmaf(wv, m[j].w, rw);
        }
    }

    // reduce read accumulators (512 -> 8 lanes); rank writes its own 128 B
    s_r[tid] = make_float4(rx, ry, rz, rw);
    __syncthreads();
#pragma unroll
    for (int s = 256; s >= 8; s >>= 1) {
        if (tid < s) {
            float4 x = s_r[tid], y = s_r[tid + s];
            x.x += y.x; x.y += y.y; x.z += y.z; x.w += y.w;
            s_r[tid] = x;
        }
        __syncthreads();
    }
    if (tid < 8)
        __stcs((float4*)(ob + rank * 32 + tid * 4), s_r[tid]);  // read row half
}

// ---------------------------------------------------------------------------
extern "C" void kernel_launch(void* const* d_in, const int* in_sizes, int n_in,
                              void* d_out, int out_size) {
    const float* mem   = (const float*)d_in[0];
    const float* kk    = (const float*)d_in[1];
    const float* beta  = (const float*)d_in[2];
    const float* gg    = (const float*)d_in[3];
    const float* ss    = (const float*)d_in[4];
    const float* gamma = (const float*)d_in[5];
    const float* wprev = (const float*)d_in[6];
    const float* ee    = (const float*)d_in[7];
    const float* aa    = (const float*)d_in[8];
    float* out = (float*)d_out;

    fused_ntm<<<2 * Bdim, 512>>>(mem, kk, beta, gg, ss, gamma, wprev, ee, aa, out);
}